// round 1
// baseline (speedup 1.0000x reference)
#include <cuda_runtime.h>
#include <math.h>

#define NN 50000
#define E_RAW 800000
#define E_TOT (E_RAW + NN)

// ---------------- scratch (device globals; no cudaMalloc allowed) ----------------
__device__ float g_bufA[(size_t)NN * 256];   // xp scratch
__device__ float g_bufB[(size_t)NN * 256];   // hidden activations
__device__ float g_s[NN * 4];
__device__ float g_d[NN * 4];
__device__ int   g_counts[NN];
__device__ int   g_row_ptr[NN + 1];
__device__ int   g_row_fill[NN];
__device__ int   g_col_src[E_TOT];

// ---------------- CSR build ----------------
__global__ void k_zero_counts() {
    int i = blockIdx.x * blockDim.x + threadIdx.x;
    if (i < NN) g_counts[i] = 0;
}

__global__ void k_build_count(const int* __restrict__ ei) {
    int e = blockIdx.x * blockDim.x + threadIdx.x;
    if (e >= E_TOT) return;
    int dst = (e < E_RAW) ? ei[E_RAW + e] : (e - E_RAW);
    atomicAdd(&g_counts[dst], 1);
}

__global__ void k_scan() {
    __shared__ int sh[1024];
    __shared__ int carry_sh;
    int tid = threadIdx.x;
    if (tid == 0) { carry_sh = 0; g_row_ptr[0] = 0; }
    __syncthreads();
    for (int base = 0; base < NN; base += 1024) {
        int i = base + tid;
        int v = (i < NN) ? g_counts[i] : 0;
        sh[tid] = v;
        __syncthreads();
        for (int off = 1; off < 1024; off <<= 1) {
            int t = (tid >= off) ? sh[tid - off] : 0;
            __syncthreads();
            sh[tid] += t;
            __syncthreads();
        }
        int carry = carry_sh;
        if (i < NN) {
            g_row_ptr[i + 1] = sh[tid] + carry;
            g_row_fill[i] = (tid == 0 ? carry : sh[tid - 1] + carry);
        }
        __syncthreads();
        if (tid == 0) carry_sh += sh[1023];
        __syncthreads();
    }
}

__global__ void k_scatter(const int* __restrict__ ei) {
    int e = blockIdx.x * blockDim.x + threadIdx.x;
    if (e >= E_TOT) return;
    int s_, d_;
    if (e < E_RAW) { s_ = ei[e]; d_ = ei[E_RAW + e]; }
    else           { s_ = d_ = e - E_RAW; }
    int pos = atomicAdd(&g_row_fill[d_], 1);
    g_col_src[pos] = s_;
}

// ---------------- GEMM: C[N,M] = A[N,K] @ B[K,M] (fp32) ----------------
__global__ void k_gemm(const float* __restrict__ A, const float* __restrict__ B,
                       float* __restrict__ C, int N, int K, int M) {
    __shared__ float As[16][64];
    __shared__ float Bs[16][64];
    int tid = threadIdx.x;
    int tx = tid & 15, ty = tid >> 4;
    int rowBase = blockIdx.y * 64, colBase = blockIdx.x * 64;
    float acc[4][4] = {};

    int lr = tid >> 2;        // 0..63 tile row for A load
    int lk = (tid & 3) * 4;   // k offset
    int br = tid >> 4;        // 0..15 k row for B load
    int bc = (tid & 15) * 4;

    for (int kb = 0; kb < K; kb += 16) {
        float4 av = make_float4(0.f, 0.f, 0.f, 0.f);
        int ar = rowBase + lr;
        if (ar < N) av = *(const float4*)(A + (size_t)ar * K + kb + lk);
        As[lk + 0][lr] = av.x;
        As[lk + 1][lr] = av.y;
        As[lk + 2][lr] = av.z;
        As[lk + 3][lr] = av.w;
        float4 bv = *(const float4*)(B + (size_t)(kb + br) * M + colBase + bc);
        *(float4*)&Bs[br][bc] = bv;
        __syncthreads();
#pragma unroll
        for (int kk = 0; kk < 16; kk++) {
            float a[4], b[4];
#pragma unroll
            for (int i = 0; i < 4; i++) a[i] = As[kk][ty * 4 + i];
#pragma unroll
            for (int j = 0; j < 4; j++) b[j] = Bs[kk][tx * 4 + j];
#pragma unroll
            for (int i = 0; i < 4; i++)
#pragma unroll
                for (int j = 0; j < 4; j++)
                    acc[i][j] += a[i] * b[j];
        }
        __syncthreads();
    }
#pragma unroll
    for (int i = 0; i < 4; i++) {
        int r = rowBase + ty * 4 + i;
        if (r < N) {
#pragma unroll
            for (int j = 0; j < 4; j++)
                C[(size_t)r * M + colBase + tx * 4 + j] = acc[i][j];
        }
    }
}

// ---------------- per-node attention scores ----------------
__global__ void k_scores(const float* __restrict__ xp, const float* __restrict__ a_src,
                         const float* __restrict__ a_dst, float* __restrict__ s,
                         float* __restrict__ d, int H, int C) {
    int gw = (blockIdx.x * blockDim.x + threadIdx.x) >> 5;
    int lane = threadIdx.x & 31;
    if (gw >= NN * H) return;
    int n = gw / H, h = gw - n * H;
    const float* row = xp + (size_t)n * H * C + h * C;
    float ss = 0.f, dd = 0.f;
    for (int c = lane; c < C; c += 32) {
        float v = row[c];
        ss += v * a_src[h * C + c];
        dd += v * a_dst[h * C + c];
    }
#pragma unroll
    for (int off = 16; off; off >>= 1) {
        ss += __shfl_xor_sync(0xffffffffu, ss, off);
        dd += __shfl_xor_sync(0xffffffffu, dd, off);
    }
    if (lane == 0) { s[n * H + h] = ss; d[n * H + h] = dd; }
}

// ---------------- gather aggregation: one block per destination node ----------------
template <int H, int C, bool ELU>
__global__ void k_aggregate(const float* __restrict__ xp, const float* __restrict__ sarr,
                            const float* __restrict__ darr, const float* __restrict__ bias,
                            float* __restrict__ out) {
    constexpr int CH = H * C;
    constexpr int NW = CH / 32;
    constexpr int CHUNK = 64;
    __shared__ float m_sh[H];
    __shared__ float zinv_sh[H];
    __shared__ float red[NW][H];
    __shared__ float alpha_sh[CHUNK][H];
    __shared__ int src_sh[CHUNK];

    int n = blockIdx.x;
    int tid = threadIdx.x;
    int lane = tid & 31, warp = tid >> 5;
    int beg = g_row_ptr[n];
    int deg = g_row_ptr[n + 1] - beg;

    float dn[H];
#pragma unroll
    for (int h = 0; h < H; h++) dn[h] = darr[n * H + h];

    // pass 1: per-head max of leaky_relu(s[src]+d[n])
    float mx[H];
#pragma unroll
    for (int h = 0; h < H; h++) mx[h] = -1e30f;
    for (int i = tid; i < deg; i += CH) {
        int sr = g_col_src[beg + i];
#pragma unroll
        for (int h = 0; h < H; h++) {
            float e = sarr[sr * H + h] + dn[h];
            e = e > 0.f ? e : 0.2f * e;
            mx[h] = fmaxf(mx[h], e);
        }
    }
#pragma unroll
    for (int h = 0; h < H; h++)
#pragma unroll
        for (int off = 16; off; off >>= 1)
            mx[h] = fmaxf(mx[h], __shfl_xor_sync(0xffffffffu, mx[h], off));
    if (lane == 0)
#pragma unroll
        for (int h = 0; h < H; h++) red[warp][h] = mx[h];
    __syncthreads();
    if (warp == 0) {
#pragma unroll
        for (int h = 0; h < H; h++) {
            float v = (lane < NW) ? red[lane][h] : -1e30f;
#pragma unroll
            for (int off = 16; off; off >>= 1)
                v = fmaxf(v, __shfl_xor_sync(0xffffffffu, v, off));
            if (lane == 0) m_sh[h] = v;
        }
    }
    __syncthreads();

    // pass 2: sum of exp(e - m)
    float sm[H];
#pragma unroll
    for (int h = 0; h < H; h++) sm[h] = 0.f;
    for (int i = tid; i < deg; i += CH) {
        int sr = g_col_src[beg + i];
#pragma unroll
        for (int h = 0; h < H; h++) {
            float e = sarr[sr * H + h] + dn[h];
            e = e > 0.f ? e : 0.2f * e;
            sm[h] += __expf(e - m_sh[h]);
        }
    }
#pragma unroll
    for (int h = 0; h < H; h++)
#pragma unroll
        for (int off = 16; off; off >>= 1)
            sm[h] += __shfl_xor_sync(0xffffffffu, sm[h], off);
    if (lane == 0)
#pragma unroll
        for (int h = 0; h < H; h++) red[warp][h] = sm[h];
    __syncthreads();
    if (warp == 0) {
#pragma unroll
        for (int h = 0; h < H; h++) {
            float v = (lane < NW) ? red[lane][h] : 0.f;
#pragma unroll
            for (int off = 16; off; off >>= 1)
                v += __shfl_xor_sync(0xffffffffu, v, off);
            if (lane == 0) zinv_sh[h] = 1.f / (v + 1e-16f);
        }
    }
    __syncthreads();

    // pass 3: weighted gather-aggregate; thread tid owns channel tid
    float acc = 0.f;
    const int hc = tid / C;
    for (int base = 0; base < deg; base += CHUNK) {
        int cnt = min(CHUNK, deg - base);
        __syncthreads();
        if (tid < cnt) {
            int sr = g_col_src[beg + base + tid];
            src_sh[tid] = sr;
#pragma unroll
            for (int h = 0; h < H; h++) {
                float e = sarr[sr * H + h] + dn[h];
                e = e > 0.f ? e : 0.2f * e;
                alpha_sh[tid][h] = __expf(e - m_sh[h]) * zinv_sh[h];
            }
        }
        __syncthreads();
        for (int j = 0; j < cnt; j++)
            acc += xp[(size_t)src_sh[j] * CH + tid] * alpha_sh[j][hc];
    }
    float v = acc + bias[tid];
    if (ELU) v = v > 0.f ? v : (__expf(v) - 1.f);
    out[(size_t)n * CH + tid] = v;
}

// ---------------- launch ----------------
extern "C" void kernel_launch(void* const* d_in, const int* in_sizes, int n_in,
                              void* d_out, int out_size) {
    const float* x      = (const float*)d_in[0];
    const int*   ei     = (const int*)d_in[1];
    const float* W0     = (const float*)d_in[2];
    const float* a_src0 = (const float*)d_in[3];
    const float* a_dst0 = (const float*)d_in[4];
    const float* b0     = (const float*)d_in[5];
    const float* W1     = (const float*)d_in[6];
    const float* a_src1 = (const float*)d_in[7];
    const float* a_dst1 = (const float*)d_in[8];
    const float* b1     = (const float*)d_in[9];
    const float* W2     = (const float*)d_in[10];
    const float* a_src2 = (const float*)d_in[11];
    const float* a_dst2 = (const float*)d_in[12];
    const float* b2     = (const float*)d_in[13];

    float *bufA, *bufB, *s, *d;
    cudaGetSymbolAddress((void**)&bufA, g_bufA);
    cudaGetSymbolAddress((void**)&bufB, g_bufB);
    cudaGetSymbolAddress((void**)&s, g_s);
    cudaGetSymbolAddress((void**)&d, g_d);

    // CSR build (per-launch, graph-capturable)
    k_zero_counts<<<(NN + 255) / 256, 256>>>();
    k_build_count<<<(E_TOT + 255) / 256, 256>>>(ei);
    k_scan<<<1, 1024>>>();
    k_scatter<<<(E_TOT + 255) / 256, 256>>>(ei);

    dim3 gHC(256 / 64, (NN + 63) / 64);
    dim3 gO(128 / 64, (NN + 63) / 64);

    // layer 0: x(N,128) @ W0 -> xp ; scores ; aggregate (+bias, elu) -> bufB
    k_gemm<<<gHC, 256>>>(x, W0, bufA, NN, 128, 256);
    k_scores<<<(NN * 4 * 32 + 255) / 256, 256>>>(bufA, a_src0, a_dst0, s, d, 4, 64);
    k_aggregate<4, 64, true><<<NN, 256>>>(bufA, s, d, b0, bufB);

    // layer 1
    k_gemm<<<gHC, 256>>>(bufB, W1, bufA, NN, 256, 256);
    k_scores<<<(NN * 4 * 32 + 255) / 256, 256>>>(bufA, a_src1, a_dst1, s, d, 4, 64);
    k_aggregate<4, 64, true><<<NN, 256>>>(bufA, s, d, b1, bufB);

    // layer 2: H=1, C=128, no elu, write d_out directly
    k_gemm<<<gO, 256>>>(bufB, W2, bufA, NN, 256, 128);
    k_scores<<<(NN * 1 * 32 + 255) / 256, 256>>>(bufA, a_src2, a_dst2, s, d, 1, 128);
    k_aggregate<1, 128, false><<<NN, 128>>>(bufA, s, d, b2, (float*)d_out);
}

// round 3
// speedup vs baseline: 1.7847x; 1.7847x over previous
#include <cuda_runtime.h>
#include <math.h>
#include <stdint.h>

#define NN 50000
#define E_RAW 800000
#define E_TOT (E_RAW + NN)

// ---------------- scratch ----------------
__device__ float g_bufA[(size_t)NN * 256];
__device__ float g_bufB[(size_t)NN * 256];
__device__ float g_s[NN * 4];
__device__ float g_d[NN * 4];
__device__ int   g_counts[NN];
__device__ int   g_row_ptr[NN + 1];
__device__ int   g_row_fill[NN];
__device__ int   g_col_src[E_TOT];

// ---------------- CSR build ----------------
__global__ void k_build_count(const int* __restrict__ ei) {
    int e = blockIdx.x * blockDim.x + threadIdx.x;
    if (e >= E_TOT) return;
    int dst = (e < E_RAW) ? ei[E_RAW + e] : (e - E_RAW);
    atomicAdd(&g_counts[dst], 1);
}

// one block, 1024 threads: serial chunk per thread + warp/block scan
__global__ void k_scan() {
    const int CH = (NN + 1023) / 1024;   // 49
    int t = threadIdx.x;
    int lane = t & 31, warp = t >> 5;
    int beg = t * CH;
    int end = min(beg + CH, NN);
    int s = 0;
    for (int i = beg; i < end; i++) s += g_counts[i];

    // inclusive warp scan
    int v = s;
#pragma unroll
    for (int off = 1; off < 32; off <<= 1) {
        int u = __shfl_up_sync(0xffffffffu, v, off);
        if (lane >= off) v += u;
    }
    __shared__ int wsum[32];
    if (lane == 31) wsum[warp] = v;
    __syncthreads();
    if (warp == 0) {
        int w = wsum[lane];
#pragma unroll
        for (int off = 1; off < 32; off <<= 1) {
            int u = __shfl_up_sync(0xffffffffu, w, off);
            if (lane >= off) w += u;
        }
        wsum[lane] = w;
    }
    __syncthreads();
    int excl = v - s + (warp ? wsum[warp - 1] : 0);

    int p = excl;
    for (int i = beg; i < end; i++) {
        g_row_fill[i] = p;
        p += g_counts[i];
        g_row_ptr[i + 1] = p;
    }
    if (t == 0) g_row_ptr[0] = 0;
}

__global__ void k_scatter(const int* __restrict__ ei) {
    int e = blockIdx.x * blockDim.x + threadIdx.x;
    if (e >= E_TOT) return;
    int s_, d_;
    if (e < E_RAW) { s_ = ei[e]; d_ = ei[E_RAW + e]; }
    else           { s_ = d_ = e - E_RAW; }
    int pos = atomicAdd(&g_row_fill[d_], 1);
    g_col_src[pos] = s_;
}

// ---------------- tf32 tensor-core GEMM ----------------
__device__ __forceinline__ uint32_t f2tf32(float x) {
    uint32_t r;
    asm("cvt.rna.tf32.f32 %0, %1;" : "=r"(r) : "f"(x));
    return r;
}

__device__ __forceinline__ void mma_tf32(float* c, const uint32_t* a, const uint32_t* b) {
    asm volatile(
        "mma.sync.aligned.m16n8k8.row.col.f32.tf32.tf32.f32 "
        "{%0,%1,%2,%3}, {%4,%5,%6,%7}, {%8,%9}, {%0,%1,%2,%3};"
        : "+f"(c[0]), "+f"(c[1]), "+f"(c[2]), "+f"(c[3])
        : "r"(a[0]), "r"(a[1]), "r"(a[2]), "r"(a[3]), "r"(b[0]), "r"(b[1]));
}

// C[N,M] = A[N,K] @ B[K,M]; block tile 128x64, K-step 32, 8 warps
__global__ void k_gemm_tc(const float* __restrict__ A, const float* __restrict__ B,
                          float* __restrict__ C, int N, int K, int M) {
    __shared__ __align__(16) uint32_t As[128][36];  // pad 36: banks 4g+t distinct
    __shared__ __align__(16) uint32_t Bs[32][68];   // pad 68: banks 4t+g distinct

    int tid = threadIdx.x;
    int lane = tid & 31, wid = tid >> 5;
    int warp_m = wid & 1, warp_n = wid >> 1;     // 2 x 4 warp grid
    int g = lane >> 2, t = lane & 3;
    int rowBase = blockIdx.y * 128, colBase = blockIdx.x * 64;

    float acc[4][2][4] = {};

    for (int kb = 0; kb < K; kb += 32) {
        // load A tile 128x32 (1024 float4, 4/thread)
#pragma unroll
        for (int i = 0; i < 4; i++) {
            int idx = tid + i * 256;
            int r = idx >> 3, c4 = (idx & 7) * 4;
            float4 v = make_float4(0.f, 0.f, 0.f, 0.f);
            int gr = rowBase + r;
            if (gr < N) v = *(const float4*)(A + (size_t)gr * K + kb + c4);
            uint4 u;
            u.x = f2tf32(v.x); u.y = f2tf32(v.y); u.z = f2tf32(v.z); u.w = f2tf32(v.w);
            *(uint4*)&As[r][c4] = u;
        }
        // load B tile 32x64 (512 float4, 2/thread)
#pragma unroll
        for (int i = 0; i < 2; i++) {
            int idx = tid + i * 256;
            int r = idx >> 4, c4 = (idx & 15) * 4;
            float4 v = *(const float4*)(B + (size_t)(kb + r) * M + colBase + c4);
            uint4 u;
            u.x = f2tf32(v.x); u.y = f2tf32(v.y); u.z = f2tf32(v.z); u.w = f2tf32(v.w);
            *(uint4*)&Bs[r][c4] = u;
        }
        __syncthreads();

#pragma unroll
        for (int kk = 0; kk < 32; kk += 8) {
            uint32_t bf[2][2];
#pragma unroll
            for (int ni = 0; ni < 2; ni++) {
                int col = warp_n * 16 + ni * 8 + g;
                bf[ni][0] = Bs[kk + t][col];
                bf[ni][1] = Bs[kk + t + 4][col];
            }
#pragma unroll
            for (int mi = 0; mi < 4; mi++) {
                int row = warp_m * 64 + mi * 16;
                uint32_t af[4];
                af[0] = As[row + g][kk + t];
                af[1] = As[row + g + 8][kk + t];
                af[2] = As[row + g][kk + t + 4];
                af[3] = As[row + g + 8][kk + t + 4];
#pragma unroll
                for (int ni = 0; ni < 2; ni++)
                    mma_tf32(acc[mi][ni], af, bf[ni]);
            }
        }
        __syncthreads();
    }

#pragma unroll
    for (int mi = 0; mi < 4; mi++) {
#pragma unroll
        for (int ni = 0; ni < 2; ni++) {
            int r0 = rowBase + warp_m * 64 + mi * 16 + g;
            int c0 = colBase + warp_n * 16 + ni * 8 + 2 * t;
            if (r0 < N)
                *(float2*)(C + (size_t)r0 * M + c0) = make_float2(acc[mi][ni][0], acc[mi][ni][1]);
            if (r0 + 8 < N)
                *(float2*)(C + (size_t)(r0 + 8) * M + c0) = make_float2(acc[mi][ni][2], acc[mi][ni][3]);
        }
    }
}

// ---------------- per-node attention scores ----------------
__global__ void k_scores(const float* __restrict__ xp, const float* __restrict__ a_src,
                         const float* __restrict__ a_dst, float* __restrict__ s,
                         float* __restrict__ d, int H, int C) {
    int gw = (blockIdx.x * blockDim.x + threadIdx.x) >> 5;
    int lane = threadIdx.x & 31;
    if (gw >= NN * H) return;
    int n = gw / H, h = gw - n * H;
    const float* row = xp + (size_t)n * H * C + h * C;
    float ss = 0.f, dd = 0.f;
    for (int c = lane; c < C; c += 32) {
        float v = row[c];
        ss += v * a_src[h * C + c];
        dd += v * a_dst[h * C + c];
    }
#pragma unroll
    for (int off = 16; off; off >>= 1) {
        ss += __shfl_xor_sync(0xffffffffu, ss, off);
        dd += __shfl_xor_sync(0xffffffffu, dd, off);
    }
    if (lane == 0) { s[n * H + h] = ss; d[n * H + h] = dd; }
}

// ---------------- aggregation (2 edge passes: max, then fused p/z/gather) ----------------
template <int H, int C, bool ELU>
__global__ void k_aggregate(const float* __restrict__ xp, const float* __restrict__ sarr,
                            const float* __restrict__ darr, const float* __restrict__ bias,
                            float* __restrict__ out) {
    constexpr int CH = H * C;
    constexpr int NW = CH / 32;
    constexpr int CHUNK = 64;
    __shared__ float m_sh[H];
    __shared__ float zinv_sh[H];
    __shared__ float red[NW][H];
    __shared__ float alpha_sh[CHUNK][H];
    __shared__ int src_sh[CHUNK];

    int n = blockIdx.x;
    int tid = threadIdx.x;
    int lane = tid & 31, warp = tid >> 5;
    int beg = g_row_ptr[n];
    int deg = g_row_ptr[n + 1] - beg;

    float dn[H];
#pragma unroll
    for (int h = 0; h < H; h++) dn[h] = darr[n * H + h];

    // pass 1: per-head max of leaky_relu(s[src]+d[n])
    float mx[H];
#pragma unroll
    for (int h = 0; h < H; h++) mx[h] = -1e30f;
    for (int i = tid; i < deg; i += CH) {
        int sr = g_col_src[beg + i];
#pragma unroll
        for (int h = 0; h < H; h++) {
            float e = sarr[sr * H + h] + dn[h];
            e = e > 0.f ? e : 0.2f * e;
            mx[h] = fmaxf(mx[h], e);
        }
    }
#pragma unroll
    for (int h = 0; h < H; h++)
#pragma unroll
        for (int off = 16; off; off >>= 1)
            mx[h] = fmaxf(mx[h], __shfl_xor_sync(0xffffffffu, mx[h], off));
    if (lane == 0)
#pragma unroll
        for (int h = 0; h < H; h++) red[warp][h] = mx[h];
    __syncthreads();
    if (warp == 0) {
#pragma unroll
        for (int h = 0; h < H; h++) {
            float v = (lane < NW) ? red[lane][h] : -1e30f;
#pragma unroll
            for (int off = 16; off; off >>= 1)
                v = fmaxf(v, __shfl_xor_sync(0xffffffffu, v, off));
            if (lane == 0) m_sh[h] = v;
        }
    }
    __syncthreads();

    // pass 2 (fused): compute p = exp(e-m), accumulate z and unnormalized features
    float zpart[H];
#pragma unroll
    for (int h = 0; h < H; h++) zpart[h] = 0.f;
    float acc = 0.f;
    const int hc = tid / C;
    for (int base = 0; base < deg; base += CHUNK) {
        int cnt = min(CHUNK, deg - base);
        __syncthreads();
        if (tid < cnt) {
            int sr = g_col_src[beg + base + tid];
            src_sh[tid] = sr;
#pragma unroll
            for (int h = 0; h < H; h++) {
                float e = sarr[sr * H + h] + dn[h];
                e = e > 0.f ? e : 0.2f * e;
                float p = __expf(e - m_sh[h]);
                alpha_sh[tid][h] = p;
                zpart[h] += p;
            }
        }
        __syncthreads();
#pragma unroll 4
        for (int j = 0; j < cnt; j++)
            acc += xp[(size_t)src_sh[j] * CH + tid] * alpha_sh[j][hc];
    }

    // block-reduce z, compute 1/z
#pragma unroll
    for (int h = 0; h < H; h++)
#pragma unroll
        for (int off = 16; off; off >>= 1)
            zpart[h] += __shfl_xor_sync(0xffffffffu, zpart[h], off);
    if (lane == 0)
#pragma unroll
        for (int h = 0; h < H; h++) red[warp][h] = zpart[h];
    __syncthreads();
    if (warp == 0) {
#pragma unroll
        for (int h = 0; h < H; h++) {
            float v = (lane < NW) ? red[lane][h] : 0.f;
#pragma unroll
            for (int off = 16; off; off >>= 1)
                v += __shfl_xor_sync(0xffffffffu, v, off);
            if (lane == 0) zinv_sh[h] = 1.f / (v + 1e-16f);
        }
    }
    __syncthreads();

    float v = acc * zinv_sh[hc] + bias[tid];
    if (ELU) v = v > 0.f ? v : (__expf(v) - 1.f);
    out[(size_t)n * CH + tid] = v;
}

// ---------------- launch ----------------
extern "C" void kernel_launch(void* const* d_in, const int* in_sizes, int n_in,
                              void* d_out, int out_size) {
    const float* x      = (const float*)d_in[0];
    const int*   ei     = (const int*)d_in[1];
    const float* W0     = (const float*)d_in[2];
    const float* a_src0 = (const float*)d_in[3];
    const float* a_dst0 = (const float*)d_in[4];
    const float* b0     = (const float*)d_in[5];
    const float* W1     = (const float*)d_in[6];
    const float* a_src1 = (const float*)d_in[7];
    const float* a_dst1 = (const float*)d_in[8];
    const float* b1     = (const float*)d_in[9];
    const float* W2     = (const float*)d_in[10];
    const float* a_src2 = (const float*)d_in[11];
    const float* a_dst2 = (const float*)d_in[12];
    const float* b2     = (const float*)d_in[13];

    float *bufA, *bufB, *s, *d;
    int* counts;
    cudaGetSymbolAddress((void**)&bufA, g_bufA);
    cudaGetSymbolAddress((void**)&bufB, g_bufB);
    cudaGetSymbolAddress((void**)&s, g_s);
    cudaGetSymbolAddress((void**)&d, g_d);
    cudaGetSymbolAddress((void**)&counts, g_counts);

    // CSR build
    cudaMemsetAsync(counts, 0, NN * sizeof(int));
    k_build_count<<<(E_TOT + 255) / 256, 256>>>(ei);
    k_scan<<<1, 1024>>>();
    k_scatter<<<(E_TOT + 255) / 256, 256>>>(ei);

    dim3 gHC(256 / 64, (NN + 127) / 128);
    dim3 gO(128 / 64, (NN + 127) / 128);

    // layer 0
    k_gemm_tc<<<gHC, 256>>>(x, W0, bufA, NN, 128, 256);
    k_scores<<<(NN * 4 * 32 + 255) / 256, 256>>>(bufA, a_src0, a_dst0, s, d, 4, 64);
    k_aggregate<4, 64, true><<<NN, 256>>>(bufA, s, d, b0, bufB);

    // layer 1
    k_gemm_tc<<<gHC, 256>>>(bufB, W1, bufA, NN, 256, 256);
    k_scores<<<(NN * 4 * 32 + 255) / 256, 256>>>(bufA, a_src1, a_dst1, s, d, 4, 64);
    k_aggregate<4, 64, true><<<NN, 256>>>(bufA, s, d, b1, bufB);

    // layer 2
    k_gemm_tc<<<gO, 256>>>(bufB, W2, bufA, NN, 256, 128);
    k_scores<<<(NN * 1 * 32 + 255) / 256, 256>>>(bufA, a_src2, a_dst2, s, d, 1, 128);
    k_aggregate<1, 128, false><<<NN, 128>>>(bufA, s, d, b2, (float*)d_out);
}

// round 7
// speedup vs baseline: 2.0579x; 1.1531x over previous
#include <cuda_runtime.h>
#include <math.h>
#include <stdint.h>

#define NN 50000
#define E_RAW 800000
#define E_TOT (E_RAW + NN)

// ---------------- scratch ----------------
__device__ float g_bufA[(size_t)NN * 256];
__device__ float g_bufB[(size_t)NN * 256];
__device__ float g_s[NN * 4];
__device__ float g_d[NN * 4];
__device__ int   g_counts[NN];
__device__ int   g_row_ptr[NN + 1];
__device__ int   g_row_fill[NN];
__device__ int   g_col_src[E_TOT];

// ---------------- CSR build ----------------
__global__ void k_build_count(const int* __restrict__ ei) {
    int e = blockIdx.x * blockDim.x + threadIdx.x;
    if (e >= E_TOT) return;
    int dst = (e < E_RAW) ? ei[E_RAW + e] : (e - E_RAW);
    atomicAdd(&g_counts[dst], 1);
}

__global__ void k_scan() {
    const int CH = (NN + 1023) / 1024;
    int t = threadIdx.x;
    int lane = t & 31, warp = t >> 5;
    int beg = t * CH;
    int end = min(beg + CH, NN);
    int s = 0;
    for (int i = beg; i < end; i++) s += g_counts[i];

    int v = s;
#pragma unroll
    for (int off = 1; off < 32; off <<= 1) {
        int u = __shfl_up_sync(0xffffffffu, v, off);
        if (lane >= off) v += u;
    }
    __shared__ int wsum[32];
    if (lane == 31) wsum[warp] = v;
    __syncthreads();
    if (warp == 0) {
        int w = wsum[lane];
#pragma unroll
        for (int off = 1; off < 32; off <<= 1) {
            int u = __shfl_up_sync(0xffffffffu, w, off);
            if (lane >= off) w += u;
        }
        wsum[lane] = w;
    }
    __syncthreads();
    int excl = v - s + (warp ? wsum[warp - 1] : 0);

    int p = excl;
    for (int i = beg; i < end; i++) {
        g_row_fill[i] = p;
        p += g_counts[i];
        g_row_ptr[i + 1] = p;
    }
    if (t == 0) g_row_ptr[0] = 0;
}

__global__ void k_scatter(const int* __restrict__ ei) {
    int e = blockIdx.x * blockDim.x + threadIdx.x;
    if (e >= E_TOT) return;
    int s_, d_;
    if (e < E_RAW) { s_ = ei[e]; d_ = ei[E_RAW + e]; }
    else           { s_ = d_ = e - E_RAW; }
    int pos = atomicAdd(&g_row_fill[d_], 1);
    g_col_src[pos] = s_;
}

// ---------------- tf32 tensor-core GEMM, double-buffered ----------------
__device__ __forceinline__ uint32_t f2tf32(float x) {
    uint32_t r;
    asm("cvt.rna.tf32.f32 %0, %1;" : "=r"(r) : "f"(x));
    return r;
}

__device__ __forceinline__ void mma_tf32(float* c, const uint32_t* a, const uint32_t* b) {
    asm volatile(
        "mma.sync.aligned.m16n8k8.row.col.f32.tf32.tf32.f32 "
        "{%0,%1,%2,%3}, {%4,%5,%6,%7}, {%8,%9}, {%0,%1,%2,%3};"
        : "+f"(c[0]), "+f"(c[1]), "+f"(c[2]), "+f"(c[3])
        : "r"(a[0]), "r"(a[1]), "r"(a[2]), "r"(a[3]), "r"(b[0]), "r"(b[1]));
}

// C[N,M] = A[N,K] @ B[K,M]; tile 128x64, K-step 32, 8 warps, double-buffered
__global__ void k_gemm_tc(const float* __restrict__ A, const float* __restrict__ B,
                          float* __restrict__ C, int N, int K, int M) {
    __shared__ __align__(16) uint32_t As[2][128][36];
    __shared__ __align__(16) uint32_t Bs[2][32][68];

    int tid = threadIdx.x;
    int lane = tid & 31, wid = tid >> 5;
    int warp_m = wid & 1, warp_n = wid >> 1;
    int g = lane >> 2, t = lane & 3;
    int rowBase = blockIdx.y * 128, colBase = blockIdx.x * 64;

    float acc[4][2][4] = {};
    float4 ra[4], rb[2];

    int a_r[4], a_c[4], b_r[2], b_c[2];
#pragma unroll
    for (int i = 0; i < 4; i++) {
        int idx = tid + i * 256;
        a_r[i] = idx >> 3; a_c[i] = (idx & 7) * 4;
    }
#pragma unroll
    for (int i = 0; i < 2; i++) {
        int idx = tid + i * 256;
        b_r[i] = idx >> 4; b_c[i] = (idx & 15) * 4;
    }

#define LOAD_TILE(kb)                                                              \
    {                                                                              \
        _Pragma("unroll")                                                          \
        for (int i = 0; i < 4; i++) {                                              \
            int gr = rowBase + a_r[i];                                             \
            ra[i] = (gr < N) ? *(const float4*)(A + (size_t)gr * K + (kb) + a_c[i])\
                             : make_float4(0.f, 0.f, 0.f, 0.f);                    \
        }                                                                          \
        _Pragma("unroll")                                                          \
        for (int i = 0; i < 2; i++)                                                \
            rb[i] = *(const float4*)(B + (size_t)((kb) + b_r[i]) * M + colBase + b_c[i]); \
    }

#define STORE_TILE(buf)                                                            \
    {                                                                              \
        _Pragma("unroll")                                                          \
        for (int i = 0; i < 4; i++) {                                              \
            uint4 u;                                                               \
            u.x = f2tf32(ra[i].x); u.y = f2tf32(ra[i].y);                          \
            u.z = f2tf32(ra[i].z); u.w = f2tf32(ra[i].w);                          \
            *(uint4*)&As[buf][a_r[i]][a_c[i]] = u;                                 \
        }                                                                          \
        _Pragma("unroll")                                                          \
        for (int i = 0; i < 2; i++) {                                              \
            uint4 u;                                                               \
            u.x = f2tf32(rb[i].x); u.y = f2tf32(rb[i].y);                          \
            u.z = f2tf32(rb[i].z); u.w = f2tf32(rb[i].w);                          \
            *(uint4*)&Bs[buf][b_r[i]][b_c[i]] = u;                                 \
        }                                                                          \
    }

    LOAD_TILE(0);
    STORE_TILE(0);
    __syncthreads();

    int nk = K >> 5;
    for (int ik = 0; ik < nk; ik++) {
        int cur = ik & 1;
        if (ik + 1 < nk) LOAD_TILE((ik + 1) << 5);

#pragma unroll
        for (int kk = 0; kk < 32; kk += 8) {
            uint32_t bf[2][2];
#pragma unroll
            for (int ni = 0; ni < 2; ni++) {
                int col = warp_n * 16 + ni * 8 + g;
                bf[ni][0] = Bs[cur][kk + t][col];
                bf[ni][1] = Bs[cur][kk + t + 4][col];
            }
#pragma unroll
            for (int mi = 0; mi < 4; mi++) {
                int row = warp_m * 64 + mi * 16;
                uint32_t af[4];
                af[0] = As[cur][row + g][kk + t];
                af[1] = As[cur][row + g + 8][kk + t];
                af[2] = As[cur][row + g][kk + t + 4];
                af[3] = As[cur][row + g + 8][kk + t + 4];
#pragma unroll
                for (int ni = 0; ni < 2; ni++)
                    mma_tf32(acc[mi][ni], af, bf[ni]);
            }
        }
        if (ik + 1 < nk) {
            STORE_TILE(cur ^ 1);
            __syncthreads();
        }
    }

#pragma unroll
    for (int mi = 0; mi < 4; mi++) {
#pragma unroll
        for (int ni = 0; ni < 2; ni++) {
            int r0 = rowBase + warp_m * 64 + mi * 16 + g;
            int c0 = colBase + warp_n * 16 + ni * 8 + 2 * t;
            if (r0 < N)
                *(float2*)(C + (size_t)r0 * M + c0) = make_float2(acc[mi][ni][0], acc[mi][ni][1]);
            if (r0 + 8 < N)
                *(float2*)(C + (size_t)(r0 + 8) * M + c0) = make_float2(acc[mi][ni][2], acc[mi][ni][3]);
        }
    }
#undef LOAD_TILE
#undef STORE_TILE
}

// ---------------- per-node attention scores ----------------
__global__ void k_scores(const float* __restrict__ xp, const float* __restrict__ a_src,
                         const float* __restrict__ a_dst, float* __restrict__ s,
                         float* __restrict__ d, int H, int C) {
    int gw = (blockIdx.x * blockDim.x + threadIdx.x) >> 5;
    int lane = threadIdx.x & 31;
    if (gw >= NN * H) return;
    int n = gw / H, h = gw - n * H;
    const float* row = xp + (size_t)n * H * C + h * C;
    float ss = 0.f, dd = 0.f;
    for (int c = lane; c < C; c += 32) {
        float v = row[c];
        ss += v * a_src[h * C + c];
        dd += v * a_dst[h * C + c];
    }
#pragma unroll
    for (int off = 16; off; off >>= 1) {
        ss += __shfl_xor_sync(0xffffffffu, ss, off);
        dd += __shfl_xor_sync(0xffffffffu, dd, off);
    }
    if (lane == 0) { s[n * H + h] = ss; d[n * H + h] = dd; }
}

// ---------------- aggregation: vectorized gather, G edges in flight ----------------
// NOTE: must be launched with exactly 256 threads for any (H, C).
template <int H, int C, bool ELU>
__global__ void k_aggregate(const float* __restrict__ xp, const float* __restrict__ sarr,
                            const float* __restrict__ darr, const float* __restrict__ bias,
                            float* __restrict__ out) {
    constexpr int CH = H * C;            // 256 or 128
    constexpr int RT = CH / 4;           // threads covering one row via float4 (64 or 32)
    constexpr int G  = 256 / RT;         // edge groups in flight (4 or 8)
    constexpr int CHUNK = 64;
    __shared__ float m_sh[H];
    __shared__ float zinv_sh[H];
    __shared__ float red[8][H];
    __shared__ float alpha_sh[CHUNK][H];
    __shared__ int src_sh[CHUNK];
    __shared__ float4 accbuf[256];

    int n = blockIdx.x;
    int tid = threadIdx.x;
    int lane = tid & 31, warp = tid >> 5;
    int beg = g_row_ptr[n];
    int deg = g_row_ptr[n + 1] - beg;

    float dn[H];
    if (H == 4) {
        float4 t4 = ((const float4*)darr)[n];
        dn[0] = t4.x; dn[1] = t4.y; dn[2] = t4.z; dn[3] = t4.w;
    } else {
        dn[0] = darr[n];
    }

    // pass 1: per-head max of leaky_relu(s[src]+d[n])
    float mx[H];
#pragma unroll
    for (int h = 0; h < H; h++) mx[h] = -1e30f;
    for (int i = tid; i < deg; i += 256) {
        int sr = g_col_src[beg + i];
        float ev[H];
        if (H == 4) {
            float4 sv = ((const float4*)sarr)[sr];
            ev[0] = sv.x; ev[1] = sv.y; ev[2] = sv.z; ev[3] = sv.w;
        } else {
            ev[0] = sarr[sr];
        }
#pragma unroll
        for (int h = 0; h < H; h++) {
            float e = ev[h] + dn[h];
            e = e > 0.f ? e : 0.2f * e;
            mx[h] = fmaxf(mx[h], e);
        }
    }
#pragma unroll
    for (int h = 0; h < H; h++)
#pragma unroll
        for (int off = 16; off; off >>= 1)
            mx[h] = fmaxf(mx[h], __shfl_xor_sync(0xffffffffu, mx[h], off));
    if (lane == 0)
#pragma unroll
        for (int h = 0; h < H; h++) red[warp][h] = mx[h];
    __syncthreads();
    if (warp == 0) {
#pragma unroll
        for (int h = 0; h < H; h++) {
            float v = (lane < 8) ? red[lane][h] : -1e30f;
#pragma unroll
            for (int off = 4; off; off >>= 1)
                v = fmaxf(v, __shfl_xor_sync(0xffffffffu, v, off));
            if (lane == 0) m_sh[h] = v;
        }
    }
    __syncthreads();

    // pass 2 (fused): alphas + z + vectorized gather-aggregate
    float zpart[H];
#pragma unroll
    for (int h = 0; h < H; h++) zpart[h] = 0.f;
    float4 acc = make_float4(0.f, 0.f, 0.f, 0.f);
    const int g = tid / RT;              // edge group (0..G-1)
    const int sub = tid - g * RT;        // channel quad index
    const int hsel = (sub * 4) / C;      // head of my 4 channels
    const float* xbase = xp + sub * 4;

    for (int base = 0; base < deg; base += CHUNK) {
        int cnt = min(CHUNK, deg - base);
        __syncthreads();
        if (tid < cnt) {
            int sr = g_col_src[beg + base + tid];
            src_sh[tid] = sr;
            float ev[H];
            if (H == 4) {
                float4 sv = ((const float4*)sarr)[sr];
                ev[0] = sv.x; ev[1] = sv.y; ev[2] = sv.z; ev[3] = sv.w;
            } else {
                ev[0] = sarr[sr];
            }
#pragma unroll
            for (int h = 0; h < H; h++) {
                float e = ev[h] + dn[h];
                e = e > 0.f ? e : 0.2f * e;
                float p = __expf(e - m_sh[h]);
                alpha_sh[tid][h] = p;
                zpart[h] += p;
            }
        }
        __syncthreads();
#pragma unroll 2
        for (int j = g; j < cnt; j += G) {
            float4 xv = *(const float4*)(xbase + (size_t)src_sh[j] * CH);
            float a = alpha_sh[j][hsel];
            acc.x += xv.x * a;
            acc.y += xv.y * a;
            acc.z += xv.z * a;
            acc.w += xv.w * a;
        }
    }

    // block-reduce z
#pragma unroll
    for (int h = 0; h < H; h++)
#pragma unroll
        for (int off = 16; off; off >>= 1)
            zpart[h] += __shfl_xor_sync(0xffffffffu, zpart[h], off);
    if (lane == 0)
#pragma unroll
        for (int h = 0; h < H; h++) red[warp][h] = zpart[h];
    accbuf[tid] = acc;
    __syncthreads();
    if (warp == 0) {
#pragma unroll
        for (int h = 0; h < H; h++) {
            float v = (lane < 8) ? red[lane][h] : 0.f;
#pragma unroll
            for (int off = 4; off; off >>= 1)
                v += __shfl_xor_sync(0xffffffffu, v, off);
            if (lane == 0) zinv_sh[h] = 1.f / (v + 1e-16f);
        }
    }
    __syncthreads();

    // reduce acc across edge groups + normalize + bias (+elu) + store
    if (tid < RT) {
        float4 tot = accbuf[tid];
#pragma unroll
        for (int gg = 1; gg < G; gg++) {
            float4 o = accbuf[gg * RT + tid];
            tot.x += o.x; tot.y += o.y; tot.z += o.z; tot.w += o.w;
        }
        float zi = zinv_sh[(tid * 4) / C];
        float4 bv = ((const float4*)bias)[tid];
        float4 v;
        v.x = tot.x * zi + bv.x;
        v.y = tot.y * zi + bv.y;
        v.z = tot.z * zi + bv.z;
        v.w = tot.w * zi + bv.w;
        if (ELU) {
            v.x = v.x > 0.f ? v.x : (__expf(v.x) - 1.f);
            v.y = v.y > 0.f ? v.y : (__expf(v.y) - 1.f);
            v.z = v.z > 0.f ? v.z : (__expf(v.z) - 1.f);
            v.w = v.w > 0.f ? v.w : (__expf(v.w) - 1.f);
        }
        ((float4*)(out + (size_t)n * CH))[tid] = v;
    }
}

// ---------------- launch ----------------
extern "C" void kernel_launch(void* const* d_in, const int* in_sizes, int n_in,
                              void* d_out, int out_size) {
    const float* x      = (const float*)d_in[0];
    const int*   ei     = (const int*)d_in[1];
    const float* W0     = (const float*)d_in[2];
    const float* a_src0 = (const float*)d_in[3];
    const float* a_dst0 = (const float*)d_in[4];
    const float* b0     = (const float*)d_in[5];
    const float* W1     = (const float*)d_in[6];
    const float* a_src1 = (const float*)d_in[7];
    const float* a_dst1 = (const float*)d_in[8];
    const float* b1     = (const float*)d_in[9];
    const float* W2     = (const float*)d_in[10];
    const float* a_src2 = (const float*)d_in[11];
    const float* a_dst2 = (const float*)d_in[12];
    const float* b2     = (const float*)d_in[13];

    float *bufA, *bufB, *s, *d;
    int* counts;
    cudaGetSymbolAddress((void**)&bufA, g_bufA);
    cudaGetSymbolAddress((void**)&bufB, g_bufB);
    cudaGetSymbolAddress((void**)&s, g_s);
    cudaGetSymbolAddress((void**)&d, g_d);
    cudaGetSymbolAddress((void**)&counts, g_counts);

    // CSR build
    cudaMemsetAsync(counts, 0, NN * sizeof(int));
    k_build_count<<<(E_TOT + 255) / 256, 256>>>(ei);
    k_scan<<<1, 1024>>>();
    k_scatter<<<(E_TOT + 255) / 256, 256>>>(ei);

    dim3 gHC(256 / 64, (NN + 127) / 128);
    dim3 gO(128 / 64, (NN + 127) / 128);

    // layer 0
    k_gemm_tc<<<gHC, 256>>>(x, W0, bufA, NN, 128, 256);
    k_scores<<<(NN * 4 * 32 + 255) / 256, 256>>>(bufA, a_src0, a_dst0, s, d, 4, 64);
    k_aggregate<4, 64, true><<<NN, 256>>>(bufA, s, d, b0, bufB);

    // layer 1
    k_gemm_tc<<<gHC, 256>>>(bufB, W1, bufA, NN, 256, 256);
    k_scores<<<(NN * 4 * 32 + 255) / 256, 256>>>(bufA, a_src1, a_dst1, s, d, 4, 64);
    k_aggregate<4, 64, true><<<NN, 256>>>(bufA, s, d, b1, bufB);

    // layer 2: NOTE 256 threads — k_aggregate requires blockDim == 256 for all (H, C)
    k_gemm_tc<<<gO, 256>>>(bufB, W2, bufA, NN, 256, 128);
    k_scores<<<(NN * 1 * 32 + 255) / 256, 256>>>(bufA, a_src2, a_dst2, s, d, 1, 128);
    k_aggregate<1, 128, false><<<NN, 256>>>(bufA, s, d, b2, (float*)d_out);
}

// round 8
// speedup vs baseline: 2.9476x; 1.4323x over previous
#include <cuda_runtime.h>
#include <math.h>
#include <stdint.h>

#define NN 50000
#define E_RAW 800000
#define E_TOT (E_RAW + NN)

// ---------------- scratch ----------------
__device__ float g_bufA[(size_t)NN * 256];
__device__ float g_bufB[(size_t)NN * 256];
__device__ float g_s[NN * 4];
__device__ float g_d[NN * 4];
__device__ int   g_counts[NN];
__device__ int   g_row_ptr[NN + 1];
__device__ int   g_row_fill[NN];
__device__ int   g_col_src[E_TOT];

// ---------------- CSR build ----------------
__global__ void k_build_count(const int* __restrict__ ei) {
    int e = blockIdx.x * blockDim.x + threadIdx.x;
    if (e >= E_TOT) return;
    int dst = (e < E_RAW) ? ei[E_RAW + e] : (e - E_RAW);
    atomicAdd(&g_counts[dst], 1);
}

__global__ void k_scan() {
    const int CH = (NN + 1023) / 1024;
    int t = threadIdx.x;
    int lane = t & 31, warp = t >> 5;
    int beg = t * CH;
    int end = min(beg + CH, NN);
    int s = 0;
    for (int i = beg; i < end; i++) s += g_counts[i];

    int v = s;
#pragma unroll
    for (int off = 1; off < 32; off <<= 1) {
        int u = __shfl_up_sync(0xffffffffu, v, off);
        if (lane >= off) v += u;
    }
    __shared__ int wsum[32];
    if (lane == 31) wsum[warp] = v;
    __syncthreads();
    if (warp == 0) {
        int w = wsum[lane];
#pragma unroll
        for (int off = 1; off < 32; off <<= 1) {
            int u = __shfl_up_sync(0xffffffffu, w, off);
            if (lane >= off) w += u;
        }
        wsum[lane] = w;
    }
    __syncthreads();
    int excl = v - s + (warp ? wsum[warp - 1] : 0);

    int p = excl;
    for (int i = beg; i < end; i++) {
        g_row_fill[i] = p;
        p += g_counts[i];
        g_row_ptr[i + 1] = p;
    }
    if (t == 0) g_row_ptr[0] = 0;
}

__global__ void k_scatter(const int* __restrict__ ei) {
    int e = blockIdx.x * blockDim.x + threadIdx.x;
    if (e >= E_TOT) return;
    int s_, d_;
    if (e < E_RAW) { s_ = ei[e]; d_ = ei[E_RAW + e]; }
    else           { s_ = d_ = e - E_RAW; }
    int pos = atomicAdd(&g_row_fill[d_], 1);
    g_col_src[pos] = s_;
}

// ---------------- tf32 tensor-core GEMM, double-buffered ----------------
__device__ __forceinline__ uint32_t f2tf32(float x) {
    uint32_t r;
    asm("cvt.rna.tf32.f32 %0, %1;" : "=r"(r) : "f"(x));
    return r;
}

__device__ __forceinline__ void mma_tf32(float* c, const uint32_t* a, const uint32_t* b) {
    asm volatile(
        "mma.sync.aligned.m16n8k8.row.col.f32.tf32.tf32.f32 "
        "{%0,%1,%2,%3}, {%4,%5,%6,%7}, {%8,%9}, {%0,%1,%2,%3};"
        : "+f"(c[0]), "+f"(c[1]), "+f"(c[2]), "+f"(c[3])
        : "r"(a[0]), "r"(a[1]), "r"(a[2]), "r"(a[3]), "r"(b[0]), "r"(b[1]));
}

// C[N,M] = A[N,K] @ B[K,M]; tile 128x64, K-step 32, 8 warps, double-buffered
__global__ void k_gemm_tc(const float* __restrict__ A, const float* __restrict__ B,
                          float* __restrict__ C, int N, int K, int M) {
    __shared__ __align__(16) uint32_t As[2][128][36];
    __shared__ __align__(16) uint32_t Bs[2][32][68];

    int tid = threadIdx.x;
    int lane = tid & 31, wid = tid >> 5;
    int warp_m = wid & 1, warp_n = wid >> 1;
    int g = lane >> 2, t = lane & 3;
    int rowBase = blockIdx.y * 128, colBase = blockIdx.x * 64;

    float acc[4][2][4] = {};
    float4 ra[4], rb[2];

    int a_r[4], a_c[4], b_r[2], b_c[2];
#pragma unroll
    for (int i = 0; i < 4; i++) {
        int idx = tid + i * 256;
        a_r[i] = idx >> 3; a_c[i] = (idx & 7) * 4;
    }
#pragma unroll
    for (int i = 0; i < 2; i++) {
        int idx = tid + i * 256;
        b_r[i] = idx >> 4; b_c[i] = (idx & 15) * 4;
    }

#define LOAD_TILE(kb)                                                              \
    {                                                                              \
        _Pragma("unroll")                                                          \
        for (int i = 0; i < 4; i++) {                                              \
            int gr = rowBase + a_r[i];                                             \
            ra[i] = (gr < N) ? *(const float4*)(A + (size_t)gr * K + (kb) + a_c[i])\
                             : make_float4(0.f, 0.f, 0.f, 0.f);                    \
        }                                                                          \
        _Pragma("unroll")                                                          \
        for (int i = 0; i < 2; i++)                                                \
            rb[i] = *(const float4*)(B + (size_t)((kb) + b_r[i]) * M + colBase + b_c[i]); \
    }

#define STORE_TILE(buf)                                                            \
    {                                                                              \
        _Pragma("unroll")                                                          \
        for (int i = 0; i < 4; i++) {                                              \
            uint4 u;                                                               \
            u.x = f2tf32(ra[i].x); u.y = f2tf32(ra[i].y);                          \
            u.z = f2tf32(ra[i].z); u.w = f2tf32(ra[i].w);                          \
            *(uint4*)&As[buf][a_r[i]][a_c[i]] = u;                                 \
        }                                                                          \
        _Pragma("unroll")                                                          \
        for (int i = 0; i < 2; i++) {                                              \
            uint4 u;                                                               \
            u.x = f2tf32(rb[i].x); u.y = f2tf32(rb[i].y);                          \
            u.z = f2tf32(rb[i].z); u.w = f2tf32(rb[i].w);                          \
            *(uint4*)&Bs[buf][b_r[i]][b_c[i]] = u;                                 \
        }                                                                          \
    }

    LOAD_TILE(0);
    STORE_TILE(0);
    __syncthreads();

    int nk = K >> 5;
    for (int ik = 0; ik < nk; ik++) {
        int cur = ik & 1;
        if (ik + 1 < nk) LOAD_TILE((ik + 1) << 5);

#pragma unroll
        for (int kk = 0; kk < 32; kk += 8) {
            uint32_t bf[2][2];
#pragma unroll
            for (int ni = 0; ni < 2; ni++) {
                int col = warp_n * 16 + ni * 8 + g;
                bf[ni][0] = Bs[cur][kk + t][col];
                bf[ni][1] = Bs[cur][kk + t + 4][col];
            }
#pragma unroll
            for (int mi = 0; mi < 4; mi++) {
                int row = warp_m * 64 + mi * 16;
                uint32_t af[4];
                af[0] = As[cur][row + g][kk + t];
                af[1] = As[cur][row + g + 8][kk + t];
                af[2] = As[cur][row + g][kk + t + 4];
                af[3] = As[cur][row + g + 8][kk + t + 4];
#pragma unroll
                for (int ni = 0; ni < 2; ni++)
                    mma_tf32(acc[mi][ni], af, bf[ni]);
            }
        }
        if (ik + 1 < nk) {
            STORE_TILE(cur ^ 1);
            __syncthreads();
        }
    }

#pragma unroll
    for (int mi = 0; mi < 4; mi++) {
#pragma unroll
        for (int ni = 0; ni < 2; ni++) {
            int r0 = rowBase + warp_m * 64 + mi * 16 + g;
            int c0 = colBase + warp_n * 16 + ni * 8 + 2 * t;
            if (r0 < N)
                *(float2*)(C + (size_t)r0 * M + c0) = make_float2(acc[mi][ni][0], acc[mi][ni][1]);
            if (r0 + 8 < N)
                *(float2*)(C + (size_t)(r0 + 8) * M + c0) = make_float2(acc[mi][ni][2], acc[mi][ni][3]);
        }
    }
#undef LOAD_TILE
#undef STORE_TILE
}

// ---------------- per-node attention scores ----------------
__global__ void k_scores(const float* __restrict__ xp, const float* __restrict__ a_src,
                         const float* __restrict__ a_dst, float* __restrict__ s,
                         float* __restrict__ d, int H, int C) {
    int gw = (blockIdx.x * blockDim.x + threadIdx.x) >> 5;
    int lane = threadIdx.x & 31;
    if (gw >= NN * H) return;
    int n = gw / H, h = gw - n * H;
    const float* row = xp + (size_t)n * H * C + h * C;
    float ss = 0.f, dd = 0.f;
    for (int c = lane; c < C; c += 32) {
        float v = row[c];
        ss += v * a_src[h * C + c];
        dd += v * a_dst[h * C + c];
    }
#pragma unroll
    for (int off = 16; off; off >>= 1) {
        ss += __shfl_xor_sync(0xffffffffu, ss, off);
        dd += __shfl_xor_sync(0xffffffffu, dd, off);
    }
    if (lane == 0) { s[n * H + h] = ss; d[n * H + h] = dd; }
}

// ---------------- aggregation: one WARP per destination node ----------------
// 32 lanes cover the CH-float row: V float4s per lane (V=2 for CH=256, 1 for CH=128).
template <int H, int C, bool ELU>
__global__ void k_agg_warp(const float* __restrict__ xp, const float* __restrict__ sarr,
                           const float* __restrict__ darr, const float* __restrict__ bias,
                           float* __restrict__ out) {
    constexpr int CH = H * C;            // 256 or 128
    constexpr int PL = CH / 32;          // floats per lane (8 or 4)
    constexpr int V  = PL / 4;           // float4s per lane (2 or 1)
    const unsigned FULL = 0xffffffffu;

    int warp = threadIdx.x >> 5, lane = threadIdx.x & 31;
    int n = blockIdx.x * (blockDim.x >> 5) + warp;
    if (n >= NN) return;

    int beg = g_row_ptr[n];
    int deg = g_row_ptr[n + 1] - beg;

    float dn[H];
    if (H == 4) {
        float4 t4 = ((const float4*)darr)[n];
        dn[0] = t4.x; dn[1] = t4.y; dn[2] = t4.z; dn[3] = t4.w;
    } else {
        dn[0] = darr[n];
    }

    // ---- pass 1: warp max of leaky_relu(s[src]+d[n]) per head ----
    float mx[H];
#pragma unroll
    for (int h = 0; h < H; h++) mx[h] = -1e30f;
    for (int i = lane; i < deg; i += 32) {
        int sr = g_col_src[beg + i];
        float ev[H];
        if (H == 4) {
            float4 sv = ((const float4*)sarr)[sr];
            ev[0] = sv.x; ev[1] = sv.y; ev[2] = sv.z; ev[3] = sv.w;
        } else {
            ev[0] = sarr[sr];
        }
#pragma unroll
        for (int h = 0; h < H; h++) {
            float e = ev[h] + dn[h];
            e = e > 0.f ? e : 0.2f * e;
            mx[h] = fmaxf(mx[h], e);
        }
    }
#pragma unroll
    for (int h = 0; h < H; h++)
#pragma unroll
        for (int off = 16; off; off >>= 1)
            mx[h] = fmaxf(mx[h], __shfl_xor_sync(FULL, mx[h], off));

    // ---- pass 2: alphas in lane registers, broadcast via shfl, gather ----
    const int hsel = (lane * PL) / C;    // head owning this lane's channels
    const float* xbase = xp + lane * PL;
    float z[H];
#pragma unroll
    for (int h = 0; h < H; h++) z[h] = 0.f;
    float4 acc[V];
#pragma unroll
    for (int v = 0; v < V; v++) acc[v] = make_float4(0.f, 0.f, 0.f, 0.f);

    for (int base = 0; base < deg; base += 32) {
        int idx = base + lane;
        int srl = 0;
        float p[H];
#pragma unroll
        for (int h = 0; h < H; h++) p[h] = 0.f;
        if (idx < deg) {
            srl = g_col_src[beg + idx];
            float ev[H];
            if (H == 4) {
                float4 sv = ((const float4*)sarr)[srl];
                ev[0] = sv.x; ev[1] = sv.y; ev[2] = sv.z; ev[3] = sv.w;
            } else {
                ev[0] = sarr[srl];
            }
#pragma unroll
            for (int h = 0; h < H; h++) {
                float e = ev[h] + dn[h];
                e = e > 0.f ? e : 0.2f * e;
                p[h] = __expf(e - mx[h]);
                z[h] += p[h];
            }
        }
        int cnt = min(32, deg - base);
        for (int j = 0; j < cnt; j++) {
            int srj = __shfl_sync(FULL, srl, j);
            float aj;
            if (H == 4) {
                float a0 = __shfl_sync(FULL, p[0], j);
                float a1 = __shfl_sync(FULL, p[1], j);
                float a2 = __shfl_sync(FULL, p[2], j);
                float a3 = __shfl_sync(FULL, p[3], j);
                aj = hsel == 0 ? a0 : hsel == 1 ? a1 : hsel == 2 ? a2 : a3;
            } else {
                aj = __shfl_sync(FULL, p[0], j);
            }
            const float4* xr = (const float4*)(xbase + (size_t)srj * CH);
#pragma unroll
            for (int v = 0; v < V; v++) {
                float4 xv = xr[v];
                acc[v].x += xv.x * aj;
                acc[v].y += xv.y * aj;
                acc[v].z += xv.z * aj;
                acc[v].w += xv.w * aj;
            }
        }
    }

    // ---- warp-reduce z, normalize, bias (+elu), store ----
#pragma unroll
    for (int h = 0; h < H; h++)
#pragma unroll
        for (int off = 16; off; off >>= 1)
            z[h] += __shfl_xor_sync(FULL, z[h], off);
    float zi = 1.f / (z[hsel] + 1e-16f);

    float4* orow = (float4*)(out + (size_t)n * CH) + lane * V;
    const float4* brow = (const float4*)bias + lane * V;
#pragma unroll
    for (int v = 0; v < V; v++) {
        float4 bv = brow[v];
        float4 r;
        r.x = acc[v].x * zi + bv.x;
        r.y = acc[v].y * zi + bv.y;
        r.z = acc[v].z * zi + bv.z;
        r.w = acc[v].w * zi + bv.w;
        if (ELU) {
            r.x = r.x > 0.f ? r.x : (__expf(r.x) - 1.f);
            r.y = r.y > 0.f ? r.y : (__expf(r.y) - 1.f);
            r.z = r.z > 0.f ? r.z : (__expf(r.z) - 1.f);
            r.w = r.w > 0.f ? r.w : (__expf(r.w) - 1.f);
        }
        orow[v] = r;
    }
}

// ---------------- launch ----------------
extern "C" void kernel_launch(void* const* d_in, const int* in_sizes, int n_in,
                              void* d_out, int out_size) {
    const float* x      = (const float*)d_in[0];
    const int*   ei     = (const int*)d_in[1];
    const float* W0     = (const float*)d_in[2];
    const float* a_src0 = (const float*)d_in[3];
    const float* a_dst0 = (const float*)d_in[4];
    const float* b0     = (const float*)d_in[5];
    const float* W1     = (const float*)d_in[6];
    const float* a_src1 = (const float*)d_in[7];
    const float* a_dst1 = (const float*)d_in[8];
    const float* b1     = (const float*)d_in[9];
    const float* W2     = (const float*)d_in[10];
    const float* a_src2 = (const float*)d_in[11];
    const float* a_dst2 = (const float*)d_in[12];
    const float* b2     = (const float*)d_in[13];

    float *bufA, *bufB, *s, *d;
    int* counts;
    cudaGetSymbolAddress((void**)&bufA, g_bufA);
    cudaGetSymbolAddress((void**)&bufB, g_bufB);
    cudaGetSymbolAddress((void**)&s, g_s);
    cudaGetSymbolAddress((void**)&d, g_d);
    cudaGetSymbolAddress((void**)&counts, g_counts);

    // CSR build
    cudaMemsetAsync(counts, 0, NN * sizeof(int));
    k_build_count<<<(E_TOT + 255) / 256, 256>>>(ei);
    k_scan<<<1, 1024>>>();
    k_scatter<<<(E_TOT + 255) / 256, 256>>>(ei);

    dim3 gHC(256 / 64, (NN + 127) / 128);
    dim3 gO(128 / 64, (NN + 127) / 128);
    int aggBlocks = (NN + 7) / 8;   // 8 warps (nodes) per 256-thread block

    // layer 0
    k_gemm_tc<<<gHC, 256>>>(x, W0, bufA, NN, 128, 256);
    k_scores<<<(NN * 4 * 32 + 255) / 256, 256>>>(bufA, a_src0, a_dst0, s, d, 4, 64);
    k_agg_warp<4, 64, true><<<aggBlocks, 256>>>(bufA, s, d, b0, bufB);

    // layer 1
    k_gemm_tc<<<gHC, 256>>>(bufB, W1, bufA, NN, 256, 256);
    k_scores<<<(NN * 4 * 32 + 255) / 256, 256>>>(bufA, a_src1, a_dst1, s, d, 4, 64);
    k_agg_warp<4, 64, true><<<aggBlocks, 256>>>(bufA, s, d, b1, bufB);

    // layer 2
    k_gemm_tc<<<gO, 256>>>(bufB, W2, bufA, NN, 256, 128);
    k_scores<<<(NN * 1 * 32 + 255) / 256, 256>>>(bufA, a_src2, a_dst2, s, d, 1, 128);
    k_agg_warp<1, 128, false><<<aggBlocks, 256>>>(bufA, s, d, b2, (float*)d_out);
}